// round 11
// baseline (speedup 1.0000x reference)
#include <cuda_runtime.h>
#include <cuda_bf16.h>
#include <math.h>

// Problem constants (fixed by the dataset)
#define BATCH 4
#define SEQ   4096
#define HID   1024
#define NHEAD 16
#define DHEAD 64
#define CTX   128
#define CTX_START (SEQ - CTX)   // 3968
#define MROWS (BATCH * CTX)     // 512

// ---------------- scratch (device globals; zero-init, no allocation) ---------
__device__ float g_Q[MROWS * HID];
__device__ float g_K[MROWS * HID];
__device__ float g_V[MROWS * HID];
__device__ float g_Attn[MROWS * HID];
__device__ float g_OutTail[MROWS * HID];
__device__ float g_BRow[BATCH * HID];

// ---------------- sentinel: pre-fill output with 1.0f ------------------------
__global__ void init_out(float* out, int n)
{
    int i = blockIdx.x * 256 + threadIdx.x;
    if (i < n) out[i] = 1.0f;
}

// ---------------- naive QKV: one thread per output element -------------------
// idx -> (which in {Q,K,V}, row r in [0,512), col n in [0,1024))
// A row r maps to inputs row (r/128)*SEQ + CTX_START + (r%128).
__global__ void qkv_naive(const float* inputs, const float* Wq,
                          const float* Wk, const float* Wv)
{
    long long idx = (long long)blockIdx.x * 256 + threadIdx.x;
    if (idx >= 3LL * MROWS * HID) return;
    int which = (int)(idx / (MROWS * HID));
    int r     = (int)((idx / HID) % MROWS);
    int n     = (int)(idx % HID);

    const float* W = (which == 0) ? Wq : (which == 1) ? Wk : Wv;
    int grow = (r >> 7) * SEQ + CTX_START + (r & 127);
    const float* a = inputs + (size_t)grow * HID;
    const float* w = W + (size_t)n * HID;

    float acc = 0.f;
    for (int k = 0; k < HID; k++) acc += a[k] * w[k];

    float* dst = (which == 0) ? g_Q : (which == 1) ? g_K : g_V;
    dst[(size_t)r * HID + n] = acc;
}

// ---------------- naive attention: one block per (b,h,query) -----------------
// 64 threads per block. Scores in shared; serial softmax on thread 0.
__global__ void attn_naive(const int* amask)
{
    const int blk = blockIdx.x;           // 0..8191
    const int sl = blk & 127;             // query within tail window
    const int h  = (blk >> 7) & 15;
    const int b  = blk >> 11;
    const int t  = threadIdx.x;           // 0..63

    __shared__ float sc[128];
    __shared__ float wsum;

    const float* q = g_Q + ((size_t)(b * CTX + sl) * HID + h * DHEAD);

    for (int c = t; c < CTX; c += 64) {
        const float* k = g_K + ((size_t)(b * CTX + c) * HID + h * DHEAD);
        float acc = 0.f;
        for (int d = 0; d < DHEAD; d++) acc += q[d] * k[d];
        bool ok = (c <= sl) && (amask[b * SEQ + CTX_START + c] != 0);
        sc[c] = ok ? acc * 0.125f : -INFINITY;
    }
    __syncthreads();

    if (t == 0) {
        float m = -INFINITY;
        for (int c = 0; c < CTX; c++) m = fmaxf(m, sc[c]);
        float s = 0.f;
        for (int c = 0; c < CTX; c++) {
            float e = __expf(sc[c] - m);   // m==-inf -> nan, matches jax
            sc[c] = e;
            s += e;
        }
        wsum = s;
    }
    __syncthreads();

    float inv = 1.f / wsum;
    const float* v = g_V + ((size_t)(b * CTX) * HID + h * DHEAD) + t;
    float o = 0.f;
    for (int c = 0; c < CTX; c++) o += sc[c] * v[(size_t)c * HID];
    g_Attn[(size_t)(b * CTX + sl) * HID + h * DHEAD + t] = o * inv;
}

// ---------------- naive tail projection: one thread per element --------------
__global__ void wo_naive(const float* Wo)
{
    long long idx = (long long)blockIdx.x * 256 + threadIdx.x;
    if (idx >= (long long)MROWS * HID) return;
    int r = (int)(idx / HID);
    int j = (int)(idx % HID);
    const float* a = g_Attn + (size_t)r * HID;
    const float* w = Wo + (size_t)j * HID;
    float acc = 0.f;
    for (int k = 0; k < HID; k++) acc += a[k] * w[k];
    g_OutTail[(size_t)r * HID + j] = acc;
}

// ---------------- naive broadcast row: V[b, ctx 0, :] @ Wo^T -----------------
__global__ void brow_naive(const float* Wo, const int* amask)
{
    int idx = blockIdx.x * 256 + threadIdx.x;     // 0..4095
    if (idx >= BATCH * HID) return;
    int b = idx >> 10;
    int j = idx & 1023;
    const float* v = g_V + (size_t)(b * CTX) * HID;
    const float* w = Wo + (size_t)j * HID;
    float acc = 0.f;
    for (int k = 0; k < HID; k++) acc += v[k] * w[k];
    bool dead = (amask[b * SEQ + CTX_START] == 0);  // all-masked row -> NaN
    g_BRow[b * HID + j] = dead ? __int_as_float(0x7fffffff) : acc;
}

// ---------------- assemble the full [B,S,H] output ---------------------------
__global__ void fill_out(float* out)
{
    const int row = blockIdx.x;              // 0..B*SEQ-1
    const int b = row >> 12;                 // SEQ = 4096
    const int s = row & (SEQ - 1);
    const float* src = (s < CTX_START)
        ? (g_BRow + b * HID)
        : (g_OutTail + (size_t)(b * CTX + (s - CTX_START)) * HID);
    float* dst = out + (size_t)row * HID;
    for (int j = threadIdx.x; j < HID; j += 256)
        dst[j] = src[j];
}

// ---------------- launch -----------------------------------------------------
extern "C" void kernel_launch(void* const* d_in, const int* in_sizes, int n_in,
                              void* d_out, int out_size)
{
    // metadata order: inputs, attention_mask, Wq, Wk, Wv, Wo
    const float* inputs = (const float*)d_in[0];
    const int*   amask  = (const int*)d_in[1];
    const float* Wq     = (const float*)d_in[2];
    const float* Wk     = (const float*)d_in[3];
    const float* Wv     = (const float*)d_in[4];
    const float* Wo     = (const float*)d_in[5];
    float* out = (float*)d_out;
    const int n = BATCH * SEQ * HID;

    // sentinel (distinguishes "never written" from "wrote zeros")
    init_out<<<(n + 255) / 256, 256>>>(out, n);

    // 1) Q,K,V projections of the 512 context rows
    {
        long long tot = 3LL * MROWS * HID;
        qkv_naive<<<(int)((tot + 255) / 256), 256>>>(inputs, Wq, Wk, Wv);
    }

    // 2) causal windowed attention (one block per (b,h,query))
    attn_naive<<<BATCH * NHEAD * CTX, 64>>>(amask);

    // 3) broadcast row per batch
    brow_naive<<<(BATCH * HID + 255) / 256, 256>>>(Wo, amask);

    // 4) tail output projection
    {
        long long tot = (long long)MROWS * HID;
        wo_naive<<<(int)((tot + 255) / 256), 256>>>(Wo);
    }

    // 5) assemble full output
    fill_out<<<BATCH * SEQ, 256>>>(out);
}

// round 16
// speedup vs baseline: 9.3295x; 9.3295x over previous
#include <cuda_runtime.h>
#include <cuda_bf16.h>
#include <math.h>

// Problem constants (fixed by the dataset)
#define BATCH 4
#define SEQ   4096
#define HID   1024
#define NHEAD 16
#define DHEAD 64
#define CTX   128
#define CTX_START (SEQ - CTX)   // 3968
#define MROWS (BATCH * CTX)     // 512

// ---------------- scratch (device globals; zero-init, no allocation) ---------
// RULE (root cause of R1-R14 failures): these symbols are ONLY referenced from
// device code. Passing them as kernel arguments from host passes the host-side
// shadow address, which GB300's ATS happily writes to -- silently wrong.
__device__ float g_Q[MROWS * HID];
__device__ float g_K[MROWS * HID];
__device__ float g_V[MROWS * HID];
__device__ float g_Attn[MROWS * HID];
__device__ float g_OutTail[MROWS * HID];
__device__ float g_BRow[BATCH * HID];

// ---------------- shared tiled-GEMM core: C[M,N] = A[M,K] @ W[N,K]^T ---------
// 32x32 output tile, 32x32 threads, one output per thread. Coalesced loads,
// padded smem (conflict-free). All pointers are device-side values.
#define TK 32

__device__ __forceinline__ void gemm_tile_body(
    const float* __restrict__ A, const float* __restrict__ W,
    float* __restrict__ C, int bm, int bn, int mapA)
{
    __shared__ float As[32][TK + 1];
    __shared__ float Ws[32][TK + 1];

    const int tx = threadIdx.x;            // 0..31 -> output col within tile
    const int ty = threadIdx.y;            // 0..31 -> output row within tile

    const int arow = bm + ty;
    const int grow = mapA ? ((arow >> 7) * SEQ + CTX_START + (arow & 127)) : arow;
    const float* aptr = A + (size_t)grow * HID;
    const float* wptr = W + (size_t)(bn + ty) * HID;

    float acc = 0.f;
    for (int k0 = 0; k0 < HID; k0 += TK) {
        As[ty][tx] = aptr[k0 + tx];        // coalesced along tx
        Ws[ty][tx] = wptr[k0 + tx];        // coalesced along tx
        __syncthreads();
#pragma unroll
        for (int k = 0; k < TK; k++)
            acc += As[ty][k] * Ws[tx][k];  // As broadcast; Ws padded
        __syncthreads();
    }
    C[(size_t)(bm + ty) * HID + bn + tx] = acc;
}

// QKV projection: z selects (Wq->g_Q, Wk->g_K, Wv->g_V); scratch chosen in
// device code (legal symbol reference).
__global__ void __launch_bounds__(1024) qkv_gemm(
    const float* __restrict__ inputs,
    const float* __restrict__ Wq, const float* __restrict__ Wk,
    const float* __restrict__ Wv)
{
    const float* W = (blockIdx.z == 0) ? Wq : (blockIdx.z == 1) ? Wk : Wv;
    float* C       = (blockIdx.z == 0) ? g_Q : (blockIdx.z == 1) ? g_K : g_V;
    gemm_tile_body(inputs, W, C, blockIdx.y * 32, blockIdx.x * 32, 1);
}

// Tail projection: g_Attn @ Wo^T -> g_OutTail (globals referenced in device code).
__global__ void __launch_bounds__(1024) wo_gemm(const float* __restrict__ Wo)
{
    gemm_tile_body(g_Attn, Wo, g_OutTail, blockIdx.y * 32, blockIdx.x * 32, 0);
}

// ---------------- attention (UNCHANGED from passing R11) ---------------------
__global__ void attn_naive(const int* amask)
{
    const int blk = blockIdx.x;           // 0..8191
    const int sl = blk & 127;             // query within tail window
    const int h  = (blk >> 7) & 15;
    const int b  = blk >> 11;
    const int t  = threadIdx.x;           // 0..63

    __shared__ float sc[128];
    __shared__ float wsum;

    const float* q = g_Q + ((size_t)(b * CTX + sl) * HID + h * DHEAD);

    for (int c = t; c < CTX; c += 64) {
        const float* k = g_K + ((size_t)(b * CTX + c) * HID + h * DHEAD);
        float acc = 0.f;
        for (int d = 0; d < DHEAD; d++) acc += q[d] * k[d];
        bool ok = (c <= sl) && (amask[b * SEQ + CTX_START + c] != 0);
        sc[c] = ok ? acc * 0.125f : -INFINITY;
    }
    __syncthreads();

    if (t == 0) {
        float m = -INFINITY;
        for (int c = 0; c < CTX; c++) m = fmaxf(m, sc[c]);
        float s = 0.f;
        for (int c = 0; c < CTX; c++) {
            float e = __expf(sc[c] - m);   // m==-inf -> nan, matches jax
            sc[c] = e;
            s += e;
        }
        wsum = s;
    }
    __syncthreads();

    float inv = 1.f / wsum;
    const float* v = g_V + ((size_t)(b * CTX) * HID + h * DHEAD) + t;
    float o = 0.f;
    for (int c = 0; c < CTX; c++) o += sc[c] * v[(size_t)c * HID];
    g_Attn[(size_t)(b * CTX + sl) * HID + h * DHEAD + t] = o * inv;
}

// ---------------- broadcast row: warp per output, coalesced ------------------
__global__ void __launch_bounds__(256) brow_warp(const float* __restrict__ Wo,
                                                 const int* __restrict__ amask)
{
    const int gw = blockIdx.x * 8 + (threadIdx.x >> 5);   // global warp 0..4095
    if (gw >= BATCH * HID) return;
    const int b = gw >> 10;
    const int j = gw & 1023;
    const int lane = threadIdx.x & 31;

    const float* v = g_V + (size_t)(b * CTX) * HID;
    const float* w = Wo + (size_t)j * HID;
    float acc = 0.f;
    for (int k = lane; k < HID; k += 32)
        acc += v[k] * w[k];
#pragma unroll
    for (int o = 16; o; o >>= 1) acc += __shfl_xor_sync(0xffffffffu, acc, o);
    if (lane == 0) {
        bool dead = (amask[b * SEQ + CTX_START] == 0);
        g_BRow[b * HID + j] = dead ? __int_as_float(0x7fffffff) : acc;
    }
}

// ---------------- assemble the full [B,S,H] output (UNCHANGED) ---------------
__global__ void fill_out(float* out)
{
    const int row = blockIdx.x;              // 0..B*SEQ-1
    const int b = row >> 12;                 // SEQ = 4096
    const int s = row & (SEQ - 1);
    const float* src = (s < CTX_START)
        ? (g_BRow + b * HID)
        : (g_OutTail + (size_t)(b * CTX + (s - CTX_START)) * HID);
    float* dst = out + (size_t)row * HID;
    for (int j = threadIdx.x; j < HID; j += 256)
        dst[j] = src[j];
}

// ---------------- launch -----------------------------------------------------
extern "C" void kernel_launch(void* const* d_in, const int* in_sizes, int n_in,
                              void* d_out, int out_size)
{
    // metadata order: inputs, attention_mask, Wq, Wk, Wv, Wo
    const float* inputs = (const float*)d_in[0];
    const int*   amask  = (const int*)d_in[1];
    const float* Wq     = (const float*)d_in[2];
    const float* Wk     = (const float*)d_in[3];
    const float* Wv     = (const float*)d_in[4];
    const float* Wo     = (const float*)d_in[5];
    float* out = (float*)d_out;

    // 1) Q,K,V projections of the 512 context rows (tiled GEMM, z = q/k/v)
    {
        dim3 grid(HID / 32, MROWS / 32, 3);
        dim3 blk(32, 32);
        qkv_gemm<<<grid, blk>>>(inputs, Wq, Wk, Wv);
    }

    // 2) causal windowed attention (identical to passing version)
    attn_naive<<<BATCH * NHEAD * CTX, 64>>>(amask);

    // 3) broadcast row per batch (warp per output, coalesced)
    brow_warp<<<BATCH * HID / 8, 256>>>(Wo, amask);

    // 4) tail output projection (tiled GEMM)
    {
        dim3 grid(HID / 32, MROWS / 32, 1);
        dim3 blk(32, 32);
        wo_gemm<<<grid, blk>>>(Wo);
    }

    // 5) assemble full output
    fill_out<<<BATCH * SEQ, 256>>>(out);
}

// round 17
// speedup vs baseline: 31.6051x; 3.3876x over previous
#include <cuda_runtime.h>
#include <cuda_bf16.h>
#include <math.h>

// Problem constants (fixed by the dataset)
#define BATCH 4
#define SEQ   4096
#define HID   1024
#define NHEAD 16
#define DHEAD 64
#define CTX   128
#define CTX_START (SEQ - CTX)   // 3968
#define MROWS (BATCH * CTX)     // 512

// ---------------- scratch (device globals; zero-init, no allocation) ---------
// RULE: these symbols are ONLY referenced from device code. Host-passing them
// hands out the host shadow address (ATS-writable on GB300 -> silent garbage).
__device__ __align__(256) float g_Q[MROWS * HID];
__device__ __align__(256) float g_K[MROWS * HID];
__device__ __align__(256) float g_V[MROWS * HID];
__device__ __align__(256) float g_Attn[MROWS * HID];
__device__ __align__(256) float g_OutTail[MROWS * HID];
__device__ __align__(256) float g_BRow[BATCH * HID];

// ---------------- register-tiled GEMM: C[M,N] = A[M,K] @ W[N,K]^T ------------
// 64x64 block tile, BK=16, 256 threads, 4x4 outputs/thread.
// Inner loop: 8 LDS per 16 FFMA (0.5 LDS/FMA) vs 2.0 in the 1-elem version.
#define BM 64
#define BN 64
#define BK 16

__device__ __forceinline__ void gemm64_body(
    const float* __restrict__ A, const float* __restrict__ W,
    float* __restrict__ C, int bm, int bn, int mapA)
{
    __shared__ float As[BK][BM + 4];
    __shared__ float Bs[BK][BN + 4];

    const int tid = threadIdx.x;
    const int tm  = tid >> 4;       // 0..15 -> rows tm*4..+3
    const int tn  = tid & 15;       // 0..15 -> cols tn*4..+3

    const int lrow = tid >> 2;      // 0..63
    const int lc4  = tid & 3;       // 0..3 -> k-cols lc4*4..+3

    int gr = bm + lrow;
    if (mapA) gr = (gr >> 7) * SEQ + CTX_START + (gr & 127);
    const float* Aptr = A + (size_t)gr * HID + lc4 * 4;
    const float* Wptr = W + (size_t)(bn + lrow) * HID + lc4 * 4;

    float acc[4][4];
#pragma unroll
    for (int i = 0; i < 4; i++)
#pragma unroll
        for (int j = 0; j < 4; j++) acc[i][j] = 0.f;

    for (int k0 = 0; k0 < HID; k0 += BK) {
        float4 av = *(const float4*)(Aptr + k0);
        float4 bv = *(const float4*)(Wptr + k0);
        __syncthreads();
        As[lc4 * 4 + 0][lrow] = av.x;
        As[lc4 * 4 + 1][lrow] = av.y;
        As[lc4 * 4 + 2][lrow] = av.z;
        As[lc4 * 4 + 3][lrow] = av.w;
        Bs[lc4 * 4 + 0][lrow] = bv.x;
        Bs[lc4 * 4 + 1][lrow] = bv.y;
        Bs[lc4 * 4 + 2][lrow] = bv.z;
        Bs[lc4 * 4 + 3][lrow] = bv.w;
        __syncthreads();
#pragma unroll
        for (int kk = 0; kk < BK; kk++) {
            float a[4], b[4];
#pragma unroll
            for (int i = 0; i < 4; i++) a[i] = As[kk][tm * 4 + i];
#pragma unroll
            for (int j = 0; j < 4; j++) b[j] = Bs[kk][tn * 4 + j];
#pragma unroll
            for (int i = 0; i < 4; i++)
#pragma unroll
                for (int j = 0; j < 4; j++) acc[i][j] += a[i] * b[j];
        }
    }

#pragma unroll
    for (int i = 0; i < 4; i++) {
        float4 v;
        v.x = acc[i][0]; v.y = acc[i][1]; v.z = acc[i][2]; v.w = acc[i][3];
        *(float4*)(C + (size_t)(bm + tm * 4 + i) * HID + bn + tn * 4) = v;
    }
}

// QKV: blockIdx.z selects weight AND scratch output inside device code.
__global__ void __launch_bounds__(256) qkv_gemm64(
    const float* __restrict__ inputs,
    const float* __restrict__ Wq, const float* __restrict__ Wk,
    const float* __restrict__ Wv)
{
    const float* W = (blockIdx.z == 0) ? Wq : (blockIdx.z == 1) ? Wk : Wv;
    float* C       = (blockIdx.z == 0) ? g_Q : (blockIdx.z == 1) ? g_K : g_V;
    gemm64_body(inputs, W, C, blockIdx.y * BM, blockIdx.x * BN, 1);
}

__global__ void __launch_bounds__(256) wo_gemm64(const float* __restrict__ Wo)
{
    gemm64_body(g_Attn, Wo, g_OutTail, blockIdx.y * BM, blockIdx.x * BN, 0);
}

// ---------------- attention: K in shared, warp per query ---------------------
// Block per (b,h): 8 warps, each owns queries w, w+8, ... (16 each).
__global__ void __launch_bounds__(256) attn_opt(const int* __restrict__ amask)
{
    __shared__ float Ks[128][65];    // 33,280 B (static, < 48 KB)
    __shared__ float Qs[8][64];
    __shared__ float SC[8][128];
    __shared__ int   padf[128];

    const int h = blockIdx.x % NHEAD;
    const int b = blockIdx.x / NHEAD;
    const int tid = threadIdx.x;
    const int w = tid >> 5, lane = tid & 31;

    for (int idx = tid; idx < 128 * 64; idx += 256) {
        int c = idx >> 6, d = idx & 63;
        Ks[c][d] = g_K[(size_t)(b * CTX + c) * HID + h * DHEAD + d];
    }
    if (tid < 128) padf[tid] = amask[b * SEQ + CTX_START + tid];
    __syncthreads();

    const float scale = 0.125f;  // 1/sqrt(64)
    const float* Vbase = g_V + (size_t)(b * CTX) * HID + h * DHEAD;

    for (int sl = w; sl < CTX; sl += 8) {
        size_t qbase = (size_t)(b * CTX + sl) * HID + h * DHEAD;
        Qs[w][lane]      = g_Q[qbase + lane];
        Qs[w][32 + lane] = g_Q[qbase + 32 + lane];
        __syncwarp();

        float s[4];
#pragma unroll
        for (int j = 0; j < 4; j++) {
            int c = lane + j * 32;
            float acc = 0.f;
#pragma unroll
            for (int d = 0; d < 64; d++)
                acc += Qs[w][d] * Ks[c][d];
            bool ok = (c <= sl) && (padf[c] != 0);
            s[j] = ok ? acc * scale : -INFINITY;
        }
        float m = fmaxf(fmaxf(s[0], s[1]), fmaxf(s[2], s[3]));
#pragma unroll
        for (int o = 16; o; o >>= 1) m = fmaxf(m, __shfl_xor_sync(0xffffffffu, m, o));

        float o0, o1;
        if (m == -INFINITY) {
            o0 = o1 = __int_as_float(0x7fffffff);   // all-masked -> NaN (jax)
        } else {
            float p[4], psum = 0.f;
#pragma unroll
            for (int j = 0; j < 4; j++) { p[j] = __expf(s[j] - m); psum += p[j]; }
#pragma unroll
            for (int o = 16; o; o >>= 1) psum += __shfl_xor_sync(0xffffffffu, psum, o);
            float inv = 1.f / psum;
#pragma unroll
            for (int j = 0; j < 4; j++) SC[w][lane + j * 32] = p[j] * inv;
            __syncwarp();

            o0 = 0.f; o1 = 0.f;
#pragma unroll 4
            for (int c = 0; c < 128; c++) {
                float wt = SC[w][c];
                const float* vp = Vbase + (size_t)c * HID;
                o0 += wt * __ldg(vp + lane);
                o1 += wt * __ldg(vp + 32 + lane);
            }
        }
        g_Attn[qbase + lane]      = o0;
        g_Attn[qbase + 32 + lane] = o1;
        __syncwarp();
    }
}

// ---------------- broadcast row: warp per output, coalesced ------------------
__global__ void __launch_bounds__(256) brow_warp(const float* __restrict__ Wo,
                                                 const int* __restrict__ amask)
{
    const int gw = blockIdx.x * 8 + (threadIdx.x >> 5);   // 0..4095
    if (gw >= BATCH * HID) return;
    const int b = gw >> 10;
    const int j = gw & 1023;
    const int lane = threadIdx.x & 31;

    const float* v = g_V + (size_t)(b * CTX) * HID;
    const float* w = Wo + (size_t)j * HID;
    float acc = 0.f;
    for (int k = lane; k < HID; k += 32)
        acc += v[k] * w[k];
#pragma unroll
    for (int o = 16; o; o >>= 1) acc += __shfl_xor_sync(0xffffffffu, acc, o);
    if (lane == 0) {
        bool dead = (amask[b * SEQ + CTX_START] == 0);
        g_BRow[b * HID + j] = dead ? __int_as_float(0x7fffffff) : acc;
    }
}

// ---------------- assemble the full [B,S,H] output (vectorized) --------------
__global__ void __launch_bounds__(256) fill_out(float4* __restrict__ out)
{
    const int row = blockIdx.x;              // 0..B*SEQ-1
    const int b = row >> 12;                 // SEQ = 4096
    const int s = row & (SEQ - 1);
    const float4* src = (const float4*)((s < CTX_START)
        ? (g_BRow + b * HID)
        : (g_OutTail + (size_t)(b * CTX + (s - CTX_START)) * HID));
    out[(size_t)row * (HID / 4) + threadIdx.x] = src[threadIdx.x];
}

// ---------------- launch -----------------------------------------------------
extern "C" void kernel_launch(void* const* d_in, const int* in_sizes, int n_in,
                              void* d_out, int out_size)
{
    // metadata order: inputs, attention_mask, Wq, Wk, Wv, Wo
    const float* inputs = (const float*)d_in[0];
    const int*   amask  = (const int*)d_in[1];
    const float* Wq     = (const float*)d_in[2];
    const float* Wk     = (const float*)d_in[3];
    const float* Wv     = (const float*)d_in[4];
    const float* Wo     = (const float*)d_in[5];

    // 1) Q,K,V projections (register-tiled GEMM; z = q/k/v)
    {
        dim3 grid(HID / BN, MROWS / BM, 3);
        qkv_gemm64<<<grid, 256>>>(inputs, Wq, Wk, Wv);
    }

    // 2) causal windowed attention (K tile in shared, warp per query)
    attn_opt<<<BATCH * NHEAD, 256>>>(amask);

    // 3) broadcast row per batch
    brow_warp<<<BATCH * HID / 8, 256>>>(Wo, amask);

    // 4) tail output projection
    {
        dim3 grid(HID / BN, MROWS / BM, 1);
        wo_gemm64<<<grid, 256>>>(Wo);
    }

    // 5) assemble full output (float4 both sides)
    fill_out<<<BATCH * SEQ, 256>>>((float4*)d_out);
}